// round 13
// baseline (speedup 1.0000x reference)
#include <cuda_runtime.h>
#include <cuda_bf16.h>
#include <cstdint>
#include <cstddef>

#define TSTEPS 32
#define INF    27
#define HID    10
#define CHUNK  8
#define NCHUNK (TSTEPS/CHUNK)
#define XROW_W 17          // u32 words per bf16 x row (k 0..31 used, pads 0)
#define MAXBLK 2048        // 65536 / 32

// per-block gate scratch: [block][CHUNK][40][32] fp32, L2-resident working set
__device__ float g_scratch[(size_t)MAXBLK * CHUNK * 40 * 32];

__device__ __forceinline__ void cp8(uint32_t saddr, const void* gptr){
  asm volatile("cp.async.ca.shared.global [%0], [%1], 8;" :: "r"(saddr), "l"(gptr));
}
__device__ __forceinline__ float tanh_fast(float x){
  float r; asm("tanh.approx.f32 %0, %1;" : "=f"(r) : "f"(x)); return r;
}
__device__ __forceinline__ float sig_from_half(float a){   // acc holds x/2
  return fmaf(0.5f, tanh_fast(a), 0.5f);
}
__device__ __forceinline__ uint32_t bf16pair(float lo_val, float hi_val){
  uint32_t r; asm("cvt.rn.bf16x2.f32 %0, %1, %2;" : "=r"(r) : "f"(hi_val), "f"(lo_val));
  return r;
}
// L2-only load (bypass L1: scratch region is rewritten every chunk)
__device__ __forceinline__ float2 ldcg2(const float* p){
  float2 v;
  asm volatile("ld.global.cg.v2.f32 {%0,%1}, [%2];" : "=f"(v.x), "=f"(v.y) : "l"(p));
  return v;
}
#define MMA_BF16(C, A, B) \
  asm volatile("mma.sync.aligned.m16n8k16.row.col.f32.bf16.bf16.f32 " \
    "{%0,%1,%2,%3}, {%4,%5,%6,%7}, {%8,%9}, {%0,%1,%2,%3};" \
    : "+f"((C)[0]), "+f"((C)[1]), "+f"((C)[2]), "+f"((C)[3]) \
    : "r"((A)[0]), "r"((A)[1]), "r"((A)[2]), "r"((A)[3]), \
      "r"((B)[0]), "r"((B)[1]))

// Single-warp blocks, 32 elems each. Per 8-step chunk: (1) GEMM phase — 8
// steps of gates = W_ih@x + b via 3-pass bf16-split mma, stored to L2 scratch;
// (2) recurrence phase — 8 scalar steps reading gates via ld.cg.
// Fragment/index math identical to the R12-verified kernel.
__global__ void __launch_bounds__(32, 12) lstm_mma_kernel(
    const float* __restrict__ word,
    const float* __restrict__ W_ih, const float* __restrict__ W_hh,
    const float* __restrict__ b_ih, const float* __restrict__ b_hh,
    const float* __restrict__ W_fc, const float* __restrict__ b_fc,
    const float* __restrict__ W_out, const float* __restrict__ b_out,
    float* __restrict__ out, int Bn)
{
  __shared__ float s_whh[40*12];                    // i/f/o rows pre-halved
  __shared__ float s_wfc[50], s_bfc[5], s_wout[5], s_bout[1];
  __shared__ __align__(16) float   s_x[2][32*INF];  // fp32 x, double-buffered
  __shared__ __align__(8) uint32_t s_xhi[32*XROW_W];
  __shared__ __align__(8) uint32_t s_xlo[32*XROW_W];

  const int lane = threadIdx.x;
  const int gr = lane >> 2, cl = lane & 3;     // mma fragment coords
  const int half = lane & 1, p = lane >> 1;    // recurrence pairing
  const int e0 = 2*p;
  const int blockElem = blockIdx.x * 32;
  const uint32_t sx0 = (uint32_t)__cvta_generic_to_shared(&s_x[0][0]);
  float* const GB = g_scratch + (size_t)blockIdx.x * (CHUNK*40*32);

  // stage t=0 x early (432 float2 over 32 lanes)
  {
    const float2* src = (const float2*)(word + ((size_t)blockElem) * INF);
    #pragma unroll
    for (int m = 0; m < 14; m++){
      int i2 = m*32 + lane;
      if (i2 < 432) cp8(sx0 + (uint32_t)(i2*8), src + i2);
    }
    asm volatile("cp.async.commit_group;");
  }

  // ---- shared fills ----
  for (int idx = lane; idx < 40*12; idx += 32){
    int r = idx / 12, j = idx - r*12;
    float sc = (r < 20 || r >= 30) ? 0.5f : 1.0f;
    s_whh[idx] = (j < 10) ? sc * W_hh[r*10 + j] : 0.f;
  }
  for (int idx = lane; idx < 50; idx += 32) s_wfc[idx] = W_fc[idx];
  if (lane < 5) { s_bfc[lane] = b_fc[lane]; s_wout[lane] = W_out[lane]; }
  if (lane == 0) s_bout[0] = b_out[0];
  s_xhi[lane*XROW_W + 14] = 0u; s_xhi[lane*XROW_W + 15] = 0u; s_xhi[lane*XROW_W + 16] = 0u;
  s_xlo[lane*XROW_W + 14] = 0u; s_xlo[lane*XROW_W + 15] = 0u; s_xlo[lane*XROW_W + 16] = 0u;

  // ---- W_ih fragments (hi/lo bf16 split), i/f/o rows pre-halved (R12-verified) ----
  uint32_t Ahi[3][2][4], Alo[3][2][4];
  float cb0[3], cb1[3];
  #pragma unroll
  for (int mi = 0; mi < 3; mi++){
    int r0 = 16*mi + gr, r1 = r0 + 8;
    float s0 = (r0 < 20 || r0 >= 30) ? 0.5f : 1.0f;
    float s1 = (r1 < 20 || r1 >= 30) ? 0.5f : 1.0f;
    cb0[mi] = (r0 < 40) ? s0 * (b_ih[r0] + b_hh[r0]) : 0.f;
    cb1[mi] = (r1 < 40) ? s1 * (b_ih[r1] + b_hh[r1]) : 0.f;
    #pragma unroll
    for (int ki = 0; ki < 2; ki++){
      #pragma unroll
      for (int q = 0; q < 4; q++){
        int r = (q & 1) ? r1 : r0;
        int c = 16*ki + 2*cl + ((q >> 1) ? 8 : 0);
        float sc = (r < 20 || r >= 30) ? 0.5f : 1.0f;
        float w0 = (r < 40 && c     < 27) ? sc * W_ih[r*27 + c    ] : 0.f;
        float w1 = (r < 40 && c + 1 < 27) ? sc * W_ih[r*27 + c + 1] : 0.f;
        uint32_t h2 = bf16pair(w0, w1);
        float h0 = __uint_as_float(h2 << 16);
        float h1 = __uint_as_float(h2 & 0xffff0000u);
        uint32_t l2 = bf16pair(w0 - h0, w1 - h1);
        Ahi[mi][ki][q] = h2;  Alo[mi][ki][q] = l2;
      }
    }
  }
  __syncwarp();

  float hA[10], hB[10], cA[5], cB[5];
  #pragma unroll
  for (int k = 0; k < 10; k++){ hA[k]=0.f; hB[k]=0.f; }
  #pragma unroll
  for (int k = 0; k < 5;  k++){ cA[k]=0.f; cB[k]=0.f; }

  const float* whh_b = s_whh + half*12;

  #pragma unroll 1
  for (int chunk = 0; chunk < NCHUNK; chunk++){
    // ================= GEMM phase: 8 steps of gates -> scratch =============
    #pragma unroll 1
    for (int s = 0; s < CHUNK; s++){
      const int t = chunk*CHUNK + s;
      if (t + 1 < TSTEPS){
        const float2* src = (const float2*)(word + ((size_t)(t+1)*Bn + blockElem) * INF);
        uint32_t dst = sx0 + (uint32_t)(((t+1)&1) * (32*INF*4));
        #pragma unroll
        for (int m = 0; m < 14; m++){
          int i2 = m*32 + lane;
          if (i2 < 432) cp8(dst + (uint32_t)(i2*8), src + i2);
        }
        asm volatile("cp.async.commit_group;");
        asm volatile("cp.async.wait_group 1;");
      } else {
        asm volatile("cp.async.wait_group 0;");
      }
      __syncwarp();   // x[t] staged by all lanes; prior B-frag reads done

      // convert own elem row fp32 -> bf16 hi/lo
      {
        const float* xr = &s_x[t & 1][lane * INF];
        const uint32_t hb = (uint32_t)(lane * XROW_W);
        #pragma unroll
        for (int m = 0; m < 14; m++){
          float x0 = xr[2*m];
          float x1 = (2*m + 1 < INF) ? xr[2*m + 1] : 0.f;
          uint32_t h2 = bf16pair(x0, x1);
          float h0 = __uint_as_float(h2 << 16);
          float h1 = __uint_as_float(h2 & 0xffff0000u);
          uint32_t l2 = bf16pair(x0 - h0, x1 - h1);
          s_xhi[hb + m] = h2;
          s_xlo[hb + m] = l2;
        }
      }
      __syncwarp();   // conversions visible before B-frag loads

      float C[3][4][4];
      #pragma unroll
      for (int mi = 0; mi < 3; mi++)
        #pragma unroll
        for (int ni = 0; ni < 4; ni++){
          C[mi][ni][0] = cb0[mi]; C[mi][ni][1] = cb0[mi];
          C[mi][ni][2] = cb1[mi]; C[mi][ni][3] = cb1[mi];
        }
      {
        uint32_t Bf[2][4][2];
        #pragma unroll
        for (int ki = 0; ki < 2; ki++)
          #pragma unroll
          for (int ni = 0; ni < 4; ni++){
            int n = 8*ni + gr;
            Bf[ki][ni][0] = s_xhi[n*XROW_W + 8*ki + cl];
            Bf[ki][ni][1] = s_xhi[n*XROW_W + 8*ki + cl + 4];
          }
        #pragma unroll
        for (int mi = 0; mi < 3; mi++)
          #pragma unroll
          for (int ni = 0; ni < 4; ni++)
            #pragma unroll
            for (int ki = 0; ki < 2; ki++){
              MMA_BF16(C[mi][ni], Ahi[mi][ki], Bf[ki][ni]);   // Whi * xhi
              MMA_BF16(C[mi][ni], Alo[mi][ki], Bf[ki][ni]);   // Wlo * xhi
            }
        #pragma unroll
        for (int ki = 0; ki < 2; ki++)
          #pragma unroll
          for (int ni = 0; ni < 4; ni++){
            int n = 8*ni + gr;
            Bf[ki][ni][0] = s_xlo[n*XROW_W + 8*ki + cl];
            Bf[ki][ni][1] = s_xlo[n*XROW_W + 8*ki + cl + 4];
          }
        #pragma unroll
        for (int mi = 0; mi < 3; mi++)
          #pragma unroll
          for (int ni = 0; ni < 4; ni++)
            #pragma unroll
            for (int ki = 0; ki < 2; ki++)
              MMA_BF16(C[mi][ni], Ahi[mi][ki], Bf[ki][ni]);   // Whi * xlo
      }
      // store gates to scratch: G(s, row, col)
      {
        float* Gs = GB + s*(40*32);
        #pragma unroll
        for (int mi = 0; mi < 3; mi++)
          #pragma unroll
          for (int ni = 0; ni < 4; ni++){
            int row0 = 16*mi + gr;
            int col  = 8*ni + 2*cl;
            *(float2*)&Gs[row0*32 + col] = make_float2(C[mi][ni][0], C[mi][ni][1]);
            if (mi < 2)
              *(float2*)&Gs[(row0+8)*32 + col] = make_float2(C[mi][ni][2], C[mi][ni][3]);
          }
      }
    }
    __syncwarp();   // all gate stores visible before recurrence reads

    // ================= recurrence phase: 8 light scalar steps ==============
    #pragma unroll 1
    for (int s = 0; s < CHUNK; s++){
      const float* Gs = GB + s*(40*32);
      float hnA[5], hnB[5];
      #pragma unroll
      for (int kk = 0; kk < 5; kk++){
        const int ri = 2*kk + half;
        float2 vi = ldcg2(Gs + (ri     )*32 + e0);
        float2 vf = ldcg2(Gs + (ri + 10)*32 + e0);
        float2 vg = ldcg2(Gs + (ri + 20)*32 + e0);
        float2 vo = ldcg2(Gs + (ri + 30)*32 + e0);
        float ai0 = vi.x, ai1 = vi.y;
        float af0 = vf.x, af1 = vf.y;
        float ag0 = vg.x, ag1 = vg.y;
        float ao0 = vo.x, ao1 = vo.y;
        #pragma unroll
        for (int j = 0; j < 10; j++){
          float ui = whh_b[24*kk +       j];
          float uf = whh_b[24*kk + 120 + j];
          float ug = whh_b[24*kk + 240 + j];
          float uo = whh_b[24*kk + 360 + j];
          float ha = hA[j], hb = hB[j];
          ai0 = fmaf(ui, ha, ai0);  ai1 = fmaf(ui, hb, ai1);
          af0 = fmaf(uf, ha, af0);  af1 = fmaf(uf, hb, af1);
          ag0 = fmaf(ug, ha, ag0);  ag1 = fmaf(ug, hb, ag1);
          ao0 = fmaf(uo, ha, ao0);  ao1 = fmaf(uo, hb, ao1);
        }
        float i0 = sig_from_half(ai0), i1 = sig_from_half(ai1);
        float f0 = sig_from_half(af0), f1 = sig_from_half(af1);
        float g0 = tanh_fast(ag0),     g1 = tanh_fast(ag1);
        float o0 = sig_from_half(ao0), o1 = sig_from_half(ao1);
        float cn0 = fmaf(f0, cA[kk], i0*g0);
        float cn1 = fmaf(f1, cB[kk], i1*g1);
        float hv0 = o0 * tanh_fast(cn0);
        float hv1 = o1 * tanh_fast(cn1);
        cA[kk]  = fmaxf(cn0, 0.f);       // ReLU on carried cell state
        cB[kk]  = fmaxf(cn1, 0.f);
        hnA[kk] = fmaxf(hv0, 0.f);       // ReLU on carried hidden
        hnB[kk] = fmaxf(hv1, 0.f);
      }
      #pragma unroll
      for (int kk = 0; kk < 5; kk++){
        float oA = __shfl_xor_sync(0xFFFFFFFFu, hnA[kk], 1);
        float oB = __shfl_xor_sync(0xFFFFFFFFu, hnB[kk], 1);
        hA[2*kk + half]     = hnA[kk];  hA[2*kk + 1 - half] = oA;
        hB[2*kk + half]     = hnB[kk];  hB[2*kk + 1 - half] = oB;
      }
    }
    __syncwarp();   // gate reads done before next chunk overwrites scratch
  }

  // ---- head: FC(10->5) -> ReLU -> Linear(5->1) -> sigmoid ----
  if (half == 0){
    float z0 = s_bout[0], z1 = s_bout[0];
    #pragma unroll
    for (int u = 0; u < 5; u++){
      float y0 = s_bfc[u], y1 = s_bfc[u];
      #pragma unroll
      for (int k = 0; k < 10; k++){
        float w = s_wfc[u*10 + k];
        y0 = fmaf(w, hA[k], y0);
        y1 = fmaf(w, hB[k], y1);
      }
      z0 = fmaf(s_wout[u], fmaxf(y0, 0.f), z0);
      z1 = fmaf(s_wout[u], fmaxf(y1, 0.f), z1);
    }
    const int b0 = blockElem + e0;
    if (b0 + 1 < Bn){
      float2 v;
      v.x = fmaf(0.5f, tanh_fast(0.5f * z0), 0.5f);
      v.y = fmaf(0.5f, tanh_fast(0.5f * z1), 0.5f);
      *(float2*)(out + b0) = v;
    } else if (b0 < Bn){
      out[b0] = fmaf(0.5f, tanh_fast(0.5f * z0), 0.5f);
    }
  }
}

extern "C" void kernel_launch(void* const* d_in, const int* in_sizes, int n_in,
                              void* d_out, int out_size) {
  const float* word  = (const float*)d_in[0];
  const float* W_ih  = (const float*)d_in[1];
  const float* W_hh  = (const float*)d_in[2];
  const float* b_ih  = (const float*)d_in[3];
  const float* b_hh  = (const float*)d_in[4];
  const float* W_fc  = (const float*)d_in[5];
  const float* b_fc  = (const float*)d_in[6];
  const float* W_out = (const float*)d_in[7];
  const float* b_out = (const float*)d_in[8];
  float* out = (float*)d_out;

  const int Bn = in_sizes[0] / (TSTEPS * INF);   // 65536
  const int blocks = (Bn + 31) / 32;             // 2048 single-warp blocks

  lstm_mma_kernel<<<blocks, 32>>>(word, W_ih, W_hh, b_ih, b_hh,
                                  W_fc, b_fc, W_out, b_out, out, Bn);
}

// round 14
// speedup vs baseline: 1.4790x; 1.4790x over previous
#include <cuda_runtime.h>
#include <cuda_bf16.h>
#include <cstdint>
#include <cstddef>

#define TSTEPS 32
#define INF    27
#define HID    10
#define XROW_W 17   // u32 words per bf16 x row (k 0..31 used by mma, pads 0)
#define GPAD   34   // s_g row stride in floats (even -> float2-aligned stores)

__device__ __forceinline__ void cp8(uint32_t saddr, const void* gptr){
  asm volatile("cp.async.ca.shared.global [%0], [%1], 8;" :: "r"(saddr), "l"(gptr));
}
__device__ __forceinline__ float tanh_fast(float x){
  float r; asm("tanh.approx.f32 %0, %1;" : "=f"(r) : "f"(x)); return r;
}
__device__ __forceinline__ float sig_from_half(float a){   // acc holds x/2
  return fmaf(0.5f, tanh_fast(a), 0.5f);
}
__device__ __forceinline__ uint32_t bf16pair(float lo_val, float hi_val){
  uint32_t r; asm("cvt.rn.bf16x2.f32 %0, %1, %2;" : "=r"(r) : "f"(hi_val), "f"(lo_val));
  return r;
}
#define MMA_BF16(C, A, B0, B1) \
  asm volatile("mma.sync.aligned.m16n8k16.row.col.f32.bf16.bf16.f32 " \
    "{%0,%1,%2,%3}, {%4,%5,%6,%7}, {%8,%9}, {%0,%1,%2,%3};" \
    : "+f"((C)[0]), "+f"((C)[1]), "+f"((C)[2]), "+f"((C)[3]) \
    : "r"((A)[0]), "r"((A)[1]), "r"((A)[2]), "r"((A)[3]), \
      "r"(B0), "r"(B1))

// Single-warp blocks, 32 elems each, 14 blocks/SM (single wave). Per step:
// (1) convert x fp32 -> bf16 hi/lo in smem, (2) gates = W_ih@x + b via 3-pass
// bf16-split mma (W fragments register-resident), (3) gates through smem to
// the scalar recurrence (split-k lane pairs, MUFU.TANH activations).
// Fragment/index math identical to the R12-verified kernel.
__global__ void __launch_bounds__(32, 14) lstm_mma_kernel(
    const float* __restrict__ word,
    const float* __restrict__ W_ih, const float* __restrict__ W_hh,
    const float* __restrict__ b_ih, const float* __restrict__ b_hh,
    const float* __restrict__ W_fc, const float* __restrict__ b_fc,
    const float* __restrict__ W_out, const float* __restrict__ b_out,
    float* __restrict__ out, int Bn)
{
  __shared__ float s_whh[40*12];                    // i/f/o rows pre-halved
  __shared__ float s_wfc[50], s_bfc[5], s_wout[5], s_bout[1];
  __shared__ __align__(16) float   s_x[32*INF];     // fp32 x, SINGLE buffer
  __shared__ __align__(8) uint32_t s_xhi[32*XROW_W];
  __shared__ __align__(8) uint32_t s_xlo[32*XROW_W];
  __shared__ __align__(8) float    s_g[40*GPAD];    // gate preactivations

  const int lane = threadIdx.x;
  const int gr = lane >> 2, cl = lane & 3;     // mma fragment coords
  const int half = lane & 1, p = lane >> 1;    // recurrence pairing
  const int e0 = 2*p;
  const int blockElem = blockIdx.x * 32;
  const uint32_t sx0 = (uint32_t)__cvta_generic_to_shared(&s_x[0]);

  // stage t=0 x early (432 float2 over 32 lanes)
  {
    const float2* src = (const float2*)(word + ((size_t)blockElem) * INF);
    #pragma unroll
    for (int m = 0; m < 14; m++){
      int i2 = m*32 + lane;
      if (i2 < 432) cp8(sx0 + (uint32_t)(i2*8), src + i2);
    }
    asm volatile("cp.async.commit_group;");
  }

  // ---- shared fills ----
  for (int idx = lane; idx < 40*12; idx += 32){
    int r = idx / 12, j = idx - r*12;
    float sc = (r < 20 || r >= 30) ? 0.5f : 1.0f;
    s_whh[idx] = (j < 10) ? sc * W_hh[r*10 + j] : 0.f;
  }
  for (int idx = lane; idx < 50; idx += 32) s_wfc[idx] = W_fc[idx];
  if (lane < 5) { s_bfc[lane] = b_fc[lane]; s_wout[lane] = W_out[lane]; }
  if (lane == 0) s_bout[0] = b_out[0];
  s_xhi[lane*XROW_W + 14] = 0u; s_xhi[lane*XROW_W + 15] = 0u; s_xhi[lane*XROW_W + 16] = 0u;
  s_xlo[lane*XROW_W + 14] = 0u; s_xlo[lane*XROW_W + 15] = 0u; s_xlo[lane*XROW_W + 16] = 0u;

  // ---- W_ih fragments (hi/lo bf16 split), i/f/o rows pre-halved (R12-verified) ----
  uint32_t Ahi[3][2][4], Alo[3][2][4];
  float cb0[3], cb1[3];
  #pragma unroll
  for (int mi = 0; mi < 3; mi++){
    int r0 = 16*mi + gr, r1 = r0 + 8;
    float s0 = (r0 < 20 || r0 >= 30) ? 0.5f : 1.0f;
    float s1 = (r1 < 20 || r1 >= 30) ? 0.5f : 1.0f;
    cb0[mi] = (r0 < 40) ? s0 * (b_ih[r0] + b_hh[r0]) : 0.f;
    cb1[mi] = (r1 < 40) ? s1 * (b_ih[r1] + b_hh[r1]) : 0.f;
    #pragma unroll
    for (int ki = 0; ki < 2; ki++){
      #pragma unroll
      for (int q = 0; q < 4; q++){
        int r = (q & 1) ? r1 : r0;
        int c = 16*ki + 2*cl + ((q >> 1) ? 8 : 0);
        float sc = (r < 20 || r >= 30) ? 0.5f : 1.0f;
        float w0 = (r < 40 && c     < 27) ? sc * W_ih[r*27 + c    ] : 0.f;
        float w1 = (r < 40 && c + 1 < 27) ? sc * W_ih[r*27 + c + 1] : 0.f;
        uint32_t h2 = bf16pair(w0, w1);
        float h0 = __uint_as_float(h2 << 16);
        float h1 = __uint_as_float(h2 & 0xffff0000u);
        uint32_t l2 = bf16pair(w0 - h0, w1 - h1);
        Ahi[mi][ki][q] = h2;  Alo[mi][ki][q] = l2;
      }
    }
  }
  __syncwarp();

  float hA[10], hB[10], cA[5], cB[5];
  #pragma unroll
  for (int k = 0; k < 10; k++){ hA[k]=0.f; hB[k]=0.f; }
  #pragma unroll
  for (int k = 0; k < 5;  k++){ cA[k]=0.f; cB[k]=0.f; }

  const float* whh_b = s_whh + half*12;

  #pragma unroll 1
  for (int t = 0; t < TSTEPS; t++){
    // x_t staged (prologue / previous iteration). Single group in flight.
    asm volatile("cp.async.wait_group 0;");
    __syncwarp();   // all lanes' cp done; also: prior step's xhi reads done

    // ---- convert own elem row fp32 -> bf16 hi/lo ----
    {
      const float* xr = &s_x[lane * INF];
      const uint32_t hb = (uint32_t)(lane * XROW_W);
      #pragma unroll
      for (int m = 0; m < 14; m++){
        float x0 = xr[2*m];
        float x1 = (2*m + 1 < INF) ? xr[2*m + 1] : 0.f;
        uint32_t h2 = bf16pair(x0, x1);
        float h0 = __uint_as_float(h2 << 16);
        float h1 = __uint_as_float(h2 & 0xffff0000u);
        uint32_t l2 = bf16pair(x0 - h0, x1 - h1);
        s_xhi[hb + m] = h2;
        s_xlo[hb + m] = l2;
      }
    }
    __syncwarp();   // conversions visible; s_x free for restage

    // ---- stage x_{t+1} into the (now free) single buffer ----
    if (t + 1 < TSTEPS){
      const float2* src = (const float2*)(word + ((size_t)(t+1)*Bn + blockElem) * INF);
      #pragma unroll
      for (int m = 0; m < 14; m++){
        int i2 = m*32 + lane;
        if (i2 < 432) cp8(sx0 + (uint32_t)(i2*8), src + i2);
      }
      asm volatile("cp.async.commit_group;");
    }

    // ---- gates = W_ih @ x + bias via 3-pass bf16-split mma ----
    float C[3][4][4];
    #pragma unroll
    for (int mi = 0; mi < 3; mi++)
      #pragma unroll
      for (int ni = 0; ni < 4; ni++){
        C[mi][ni][0] = cb0[mi]; C[mi][ni][1] = cb0[mi];
        C[mi][ni][2] = cb1[mi]; C[mi][ni][3] = cb1[mi];
      }
    #pragma unroll
    for (int ki = 0; ki < 2; ki++){
      #pragma unroll
      for (int ni = 0; ni < 4; ni++){
        int n = 8*ni + gr;
        uint32_t bh0 = s_xhi[n*XROW_W + 8*ki + cl];
        uint32_t bh1 = s_xhi[n*XROW_W + 8*ki + cl + 4];
        #pragma unroll
        for (int mi = 0; mi < 3; mi++){
          MMA_BF16(C[mi][ni], Ahi[mi][ki], bh0, bh1);   // Whi * xhi
          MMA_BF16(C[mi][ni], Alo[mi][ki], bh0, bh1);   // Wlo * xhi
        }
        uint32_t bl0 = s_xlo[n*XROW_W + 8*ki + cl];
        uint32_t bl1 = s_xlo[n*XROW_W + 8*ki + cl + 4];
        #pragma unroll
        for (int mi = 0; mi < 3; mi++)
          MMA_BF16(C[mi][ni], Ahi[mi][ki], bl0, bl1);   // Whi * xlo
      }
    }
    // ---- store gates: C frag (gr,2cl | +8) -> s_g[row][elem] ----
    #pragma unroll
    for (int mi = 0; mi < 3; mi++)
      #pragma unroll
      for (int ni = 0; ni < 4; ni++){
        int row0 = 16*mi + gr;
        int col  = 8*ni + 2*cl;
        *(float2*)&s_g[row0*GPAD + col] = make_float2(C[mi][ni][0], C[mi][ni][1]);
        if (mi < 2)
          *(float2*)&s_g[(row0+8)*GPAD + col] = make_float2(C[mi][ni][2], C[mi][ni][3]);
      }
    __syncwarp();

    // ---- scalar recurrence; own k = 2kk + half (interleaved split-k) ----
    float hnA[5], hnB[5];
    #pragma unroll
    for (int kk = 0; kk < 5; kk++){
      const int ri = 2*kk + half;
      float ai0 = s_g[(ri     )*GPAD + e0], ai1 = s_g[(ri     )*GPAD + e0 + 1];
      float af0 = s_g[(ri + 10)*GPAD + e0], af1 = s_g[(ri + 10)*GPAD + e0 + 1];
      float ag0 = s_g[(ri + 20)*GPAD + e0], ag1 = s_g[(ri + 20)*GPAD + e0 + 1];
      float ao0 = s_g[(ri + 30)*GPAD + e0], ao1 = s_g[(ri + 30)*GPAD + e0 + 1];
      #pragma unroll
      for (int j = 0; j < 10; j++){
        float ui = whh_b[24*kk +       j];
        float uf = whh_b[24*kk + 120 + j];
        float ug = whh_b[24*kk + 240 + j];
        float uo = whh_b[24*kk + 360 + j];
        float ha = hA[j], hb = hB[j];
        ai0 = fmaf(ui, ha, ai0);  ai1 = fmaf(ui, hb, ai1);
        af0 = fmaf(uf, ha, af0);  af1 = fmaf(uf, hb, af1);
        ag0 = fmaf(ug, ha, ag0);  ag1 = fmaf(ug, hb, ag1);
        ao0 = fmaf(uo, ha, ao0);  ao1 = fmaf(uo, hb, ao1);
      }
      float i0 = sig_from_half(ai0), i1 = sig_from_half(ai1);
      float f0 = sig_from_half(af0), f1 = sig_from_half(af1);
      float g0 = tanh_fast(ag0),     g1 = tanh_fast(ag1);
      float o0 = sig_from_half(ao0), o1 = sig_from_half(ao1);
      float cn0 = fmaf(f0, cA[kk], i0*g0);
      float cn1 = fmaf(f1, cB[kk], i1*g1);
      float hv0 = o0 * tanh_fast(cn0);
      float hv1 = o1 * tanh_fast(cn1);
      cA[kk]  = fmaxf(cn0, 0.f);       // ReLU on carried cell state
      cB[kk]  = fmaxf(cn1, 0.f);
      hnA[kk] = fmaxf(hv0, 0.f);       // ReLU on carried hidden
      hnB[kk] = fmaxf(hv1, 0.f);
    }
    #pragma unroll
    for (int kk = 0; kk < 5; kk++){
      float oA = __shfl_xor_sync(0xFFFFFFFFu, hnA[kk], 1);
      float oB = __shfl_xor_sync(0xFFFFFFFFu, hnB[kk], 1);
      hA[2*kk + half]     = hnA[kk];  hA[2*kk + 1 - half] = oA;
      hB[2*kk + half]     = hnB[kk];  hB[2*kk + 1 - half] = oB;
    }
    // s_g overwrite next step is ordered by the two syncwarps at next
    // iteration's top (wait + post-convert) — warp-local memory ordering.
  }

  // ---- head: FC(10->5) -> ReLU -> Linear(5->1) -> sigmoid ----
  if (half == 0){
    float z0 = s_bout[0], z1 = s_bout[0];
    #pragma unroll
    for (int u = 0; u < 5; u++){
      float y0 = s_bfc[u], y1 = s_bfc[u];
      #pragma unroll
      for (int k = 0; k < 10; k++){
        float w = s_wfc[u*10 + k];
        y0 = fmaf(w, hA[k], y0);
        y1 = fmaf(w, hB[k], y1);
      }
      z0 = fmaf(s_wout[u], fmaxf(y0, 0.f), z0);
      z1 = fmaf(s_wout[u], fmaxf(y1, 0.f), z1);
    }
    const int b0 = blockElem + e0;
    if (b0 + 1 < Bn){
      float2 v;
      v.x = fmaf(0.5f, tanh_fast(0.5f * z0), 0.5f);
      v.y = fmaf(0.5f, tanh_fast(0.5f * z1), 0.5f);
      *(float2*)(out + b0) = v;
    } else if (b0 < Bn){
      out[b0] = fmaf(0.5f, tanh_fast(0.5f * z0), 0.5f);
    }
  }
}

extern "C" void kernel_launch(void* const* d_in, const int* in_sizes, int n_in,
                              void* d_out, int out_size) {
  const float* word  = (const float*)d_in[0];
  const float* W_ih  = (const float*)d_in[1];
  const float* W_hh  = (const float*)d_in[2];
  const float* b_ih  = (const float*)d_in[3];
  const float* b_hh  = (const float*)d_in[4];
  const float* W_fc  = (const float*)d_in[5];
  const float* b_fc  = (const float*)d_in[6];
  const float* W_out = (const float*)d_in[7];
  const float* b_out = (const float*)d_in[8];
  float* out = (float*)d_out;

  const int Bn = in_sizes[0] / (TSTEPS * INF);   // 65536
  const int blocks = (Bn + 31) / 32;             // 2048 single-warp blocks

  lstm_mma_kernel<<<blocks, 32>>>(word, W_ih, W_hh, b_ih, b_hh,
                                  W_fc, b_fc, W_out, b_out, out, Bn);
}